// round 9
// baseline (speedup 1.0000x reference)
#include <cuda_runtime.h>
#include <math.h>
#include <stddef.h>
#include <stdint.h>

// Problem dims
#define TT 1024
#define BB 256
#define XDIM 64
#define HDIM 256
#define FDIM 256
#define MM (TT*BB)          // 262144 rows for all big GEMMs

// ---------------------------------------------------------------------------
// Scratch (no cudaMalloc allowed)
// ---------------------------------------------------------------------------
__device__ float g_bufA[(size_t)MM * FDIM];   // 256 MB
__device__ float g_bufB[(size_t)MM * FDIM];   // 256 MB
__device__ float g_wr[294912];                // rounded weights, 1.2 MB

#define WR_WX0 0
#define WR_WX1 16384
#define WR_WIH 81920
#define WR_WH0 147456
#define WR_WH1 212992
#define WR_WG  278528

// ---------------------------------------------------------------------------
// helpers
// ---------------------------------------------------------------------------
__device__ __forceinline__ uint32_t f2tf32(float x) {
    uint32_t u;
    asm("cvt.rna.tf32.f32 %0, %1;" : "=r"(u) : "f"(x));
    return u;
}
__device__ __forceinline__ float roundtf(float x) {
    return __uint_as_float(f2tf32(x));
}

#define MMA_TF32(c, a0, a1, a2, a3, b0, b1)                                 \
    asm volatile("mma.sync.aligned.m16n8k8.row.col.f32.tf32.tf32.f32 "      \
                 "{%0,%1,%2,%3}, {%4,%5,%6,%7}, {%8,%9}, {%0,%1,%2,%3};"    \
                 : "+f"(c[0]), "+f"(c[1]), "+f"(c[2]), "+f"(c[3])           \
                 : "r"(a0), "r"(a1), "r"(a2), "r"(a3), "r"(b0), "r"(b1))

#define FMA2(d, a, b)                                                       \
    asm("fma.rn.f32x2 %0, %1, %2, %0;" : "+l"(d) : "l"(a), "l"(b))
#define ADD2(d, a)                                                          \
    asm("add.rn.f32x2 %0, %0, %1;" : "+l"(d) : "l"(a))
#define UNPACK2(lo, hi, d)                                                  \
    asm("mov.b64 {%0, %1}, %2;" : "=f"(lo), "=f"(hi) : "l"(d))

__device__ __forceinline__ void cp16(uint32_t dst, const void* src) {
    asm volatile("cp.async.ca.shared.global [%0], [%1], 16;\n"
                 :: "r"(dst), "l"(src));
}
__device__ __forceinline__ void cp_commit() {
    asm volatile("cp.async.commit_group;\n" ::);
}
template<int N>
__device__ __forceinline__ void cp_wait() {
    asm volatile("cp.async.wait_group %0;\n" :: "n"(N));
}

// ---------------------------------------------------------------------------
// Pre-round inputs to tf32 (idempotent; GEMMs then feed raw bits to mma)
// ---------------------------------------------------------------------------
__global__ void round_tf32_kernel(const float* __restrict__ src,
                                  float* __restrict__ dst, int n)
{
    int idx = (blockIdx.x * blockDim.x + threadIdx.x) * 4;
    if (idx < n) {
        float4 v = *(const float4*)(src + idx);
        v.x = roundtf(v.x); v.y = roundtf(v.y);
        v.z = roundtf(v.z); v.w = roundtf(v.w);
        *(float4*)(dst + idx) = v;
    }
}

// ---------------------------------------------------------------------------
// Generic k-tile compute: A fragments from swizzled smem tile [128][32],
// W (B operand, row-major [N][K]) fragments via __ldg straight from L2.
// Same fragment indexing as the verified R8 kernel.
// ---------------------------------------------------------------------------
template<int WM_AT, int WN_AT>
__device__ __forceinline__ void comp_gw(
    const float* Asl, const float* __restrict__ Wg, int K, int ktbase,
    int wm, int wn, int g, int tig, float (*c)[4])
{
#pragma unroll
    for (int s = 0; s < 4; s++) {
        const int x0 = ((2 * s) ^ g) * 4 + tig;       // k = s*8+tig
        const int x1 = ((2 * s + 1) ^ g) * 4 + tig;   // k = s*8+tig+4
        uint32_t af[WM_AT][4];
#pragma unroll
        for (int mi = 0; mi < WM_AT; mi++) {
            int rb = (wm * WM_AT + mi) * 16 + g;
            af[mi][0] = __float_as_uint(Asl[rb * 32 + x0]);
            af[mi][1] = __float_as_uint(Asl[(rb + 8) * 32 + x0]);
            af[mi][2] = __float_as_uint(Asl[rb * 32 + x1]);
            af[mi][3] = __float_as_uint(Asl[(rb + 8) * 32 + x1]);
        }
        uint32_t bf[WN_AT][2];
#pragma unroll
        for (int ni = 0; ni < WN_AT; ni++) {
            int nb = (wn * WN_AT + ni) * 8 + g;
            const float* wp = Wg + (size_t)nb * K + ktbase + s * 8 + tig;
            bf[ni][0] = __float_as_uint(__ldg(wp));
            bf[ni][1] = __float_as_uint(__ldg(wp + 4));
        }
#pragma unroll
        for (int mi = 0; mi < WM_AT; mi++)
#pragma unroll
            for (int ni = 0; ni < WN_AT; ni++)
                MMA_TF32(c[mi * WN_AT + ni], af[mi][0], af[mi][1],
                         af[mi][2], af[mi][3], bf[ni][0], bf[ni][1]);
    }
}

// Store accums (N=256 mapping: WM_AT=2, WN_AT=8) as tanh+tf32-round into the
// swizzled smem buffer S (8 k-tiles x [128][32]).
__device__ __forceinline__ void store_S_tanh(
    float* S, const float* __restrict__ bias,
    int wm, int wn, int g, int tig, float (*c)[4])
{
#pragma unroll
    for (int mi = 0; mi < 2; mi++) {
        int r0 = (wm * 2 + mi) * 16 + g;
#pragma unroll
        for (int ni = 0; ni < 8; ni++) {
            int cc = (wn * 8 + ni) * 8 + 2 * tig;
            float b0 = bias[cc], b1 = bias[cc + 1];
            float* p = c[mi * 8 + ni];
            float v0 = roundtf(tanhf(p[0] + b0));
            float v1 = roundtf(tanhf(p[1] + b1));
            float v2 = roundtf(tanhf(p[2] + b0));
            float v3 = roundtf(tanhf(p[3] + b1));
            int tilebase = (cc >> 5) * 4096;
            int swz = ((((cc >> 2) & 7)) ^ (r0 & 7)) << 2;   // r0&7 == g
            int elem = cc & 3;
            *(float2*)(S + tilebase + r0 * 32 + swz + elem) = make_float2(v0, v1);
            *(float2*)(S + tilebase + (r0 + 8) * 32 + swz + elem) = make_float2(v2, v3);
        }
    }
}

// ---------------------------------------------------------------------------
// Fused 3-layer MLP over a 128-row tile:
//   S = tanh(Ain@W1^T + b1)   (K=K1, N=256)
//   S = tanh(S@W2^T + b2)     (K=256, N=256)
//   C = S@W3^T + b3 (+b3b)    (K=256, N=N3)
// 512 threads, 16 warps. Intermediate lives in 128KB smem; W via L2 __ldg.
// All inputs (Ain, W*) must be pre-rounded to tf32 bit patterns.
// ---------------------------------------------------------------------------
#define FUSED_SMEM ((32768 + 2 * 4096) * 4)   // 163840 B

template<int K1, int N3>
__global__ __launch_bounds__(512) void fused3_kernel(
    const float* __restrict__ Ain,
    const float* __restrict__ W1, const float* __restrict__ b1,
    const float* __restrict__ W2, const float* __restrict__ b2,
    const float* __restrict__ W3, const float* __restrict__ b3,
    const float* __restrict__ b3b,
    float* __restrict__ Cout)
{
    extern __shared__ float smf[];
    float* S    = smf;            // 32768 floats (8 k-tiles x 128 x 32)
    float* Abuf = smf + 32768;    // 2 stages x 4096 floats

    const int tid  = threadIdx.x;
    const int warp = tid >> 5;
    const int lane = tid & 31;
    const int wm   = warp >> 2;    // 4x4 warp grid for N=256 phases
    const int wn   = warp & 3;
    const int g    = lane >> 2;
    const int tig  = lane & 3;
    const int m0   = blockIdx.x * 128;

    float c[16][4];

    // ---------------- Phase A: S = tanh(Ain@W1^T + b1) ----------------
#pragma unroll
    for (int i = 0; i < 16; i++)
#pragma unroll
        for (int e = 0; e < 4; e++) c[i][e] = 0.0f;

    constexpr int KT1 = K1 / 32;
    auto issueA = [&](int st, int kt) {
#pragma unroll
        for (int it = 0; it < 2; it++) {
            int ch = tid + it * 512;
            int row = ch >> 3, cc = ch & 7;
            const float* src = Ain + (size_t)(m0 + row) * K1 + kt * 32 + cc * 4;
            uint32_t dst = (uint32_t)__cvta_generic_to_shared(
                Abuf + st * 4096 + row * 32 + ((cc ^ (row & 7)) << 2));
            cp16(dst, src);
        }
    };
    issueA(0, 0); cp_commit();
    issueA(1, 1); cp_commit();     // KT1 >= 2 always (64 or 256)
    for (int kt = 0; kt < KT1; kt++) {
        cp_wait<1>();
        __syncthreads();
        comp_gw<2, 8>(Abuf + (kt & 1) * 4096, W1, K1, kt * 32,
                      wm, wn, g, tig, c);
        __syncthreads();
        if (kt + 2 < KT1) issueA(kt & 1, kt + 2);
        cp_commit();
    }
    cp_wait<0>();
    store_S_tanh(S, b1, wm, wn, g, tig, c);
    __syncthreads();

    // ---------------- Phase B: S = tanh(S@W2^T + b2) ----------------
#pragma unroll
    for (int i = 0; i < 16; i++)
#pragma unroll
        for (int e = 0; e < 4; e++) c[i][e] = 0.0f;
#pragma unroll
    for (int kt = 0; kt < 8; kt++)
        comp_gw<2, 8>(S + kt * 4096, W2, 256, kt * 32, wm, wn, g, tig, c);
    __syncthreads();                 // all warps done reading S
    store_S_tanh(S, b2, wm, wn, g, tig, c);
    __syncthreads();

    // ---------------- Phase C: Cout = S@W3^T + b3 (+b3b) ----------------
#pragma unroll
    for (int i = 0; i < 16; i++)
#pragma unroll
        for (int e = 0; e < 4; e++) c[i][e] = 0.0f;

    if constexpr (N3 == 256) {
#pragma unroll
        for (int kt = 0; kt < 8; kt++)
            comp_gw<2, 8>(S + kt * 4096, W3, 256, kt * 32, wm, wn, g, tig, c);
#pragma unroll
        for (int mi = 0; mi < 2; mi++) {
            int r0 = m0 + (wm * 2 + mi) * 16 + g;
#pragma unroll
            for (int ni = 0; ni < 8; ni++) {
                int cc = (wn * 8 + ni) * 8 + 2 * tig;
                float b0v = b3[cc], b1v = b3[cc + 1];
                if (b3b) { b0v += b3b[cc]; b1v += b3b[cc + 1]; }
                float* p = c[mi * 8 + ni];
                *(float2*)(Cout + (size_t)r0 * 256 + cc) =
                    make_float2(p[0] + b0v, p[1] + b1v);
                *(float2*)(Cout + (size_t)(r0 + 8) * 256 + cc) =
                    make_float2(p[2] + b0v, p[3] + b1v);
            }
        }
    } else {
        // N3 = 64: 8x2 warp grid, WM_AT=1, WN_AT=4
        const int wm3 = warp >> 1;
        const int wn3 = warp & 1;
#pragma unroll
        for (int kt = 0; kt < 8; kt++)
            comp_gw<1, 4>(S + kt * 4096, W3, 256, kt * 32, wm3, wn3, g, tig, c);
        int r0 = m0 + wm3 * 16 + g;
#pragma unroll
        for (int ni = 0; ni < 4; ni++) {
            int cc = (wn3 * 4 + ni) * 8 + 2 * tig;
            float b0v = b3[cc], b1v = b3[cc + 1];
            float* p = c[ni];
            *(float2*)(Cout + (size_t)r0 * 64 + cc) =
                make_float2(p[0] + b0v, p[1] + b1v);
            *(float2*)(Cout + (size_t)(r0 + 8) * 64 + cc) =
                make_float2(p[2] + b0v, p[3] + b1v);
        }
    }
}

// ---------------------------------------------------------------------------
// Recurrence v5 (unchanged from R8). 128 blocks x 512 threads, 2 batch rows.
// ---------------------------------------------------------------------------
#define R5_WSTRIDE 17
#define R5_SMEM_BYTES (512*R5_WSTRIDE*16 + 2*128*16 + 512*8)  // 147456 B

__global__ __launch_bounds__(512, 1) void recurrence5_kernel(
    const float* __restrict__ Z, const float* __restrict__ Whh,
    float* __restrict__ Hall)
{
    extern __shared__ unsigned char rsm[];
    float4*     Wsm4 = (float4*)rsm;                               // [512][17]
    ulonglong2* hs2  = (ulonglong2*)(rsm + 512 * R5_WSTRIDE * 16); // [2][128]
    float2*     red  = (float2*)(rsm + 512 * R5_WSTRIDE * 16 + 4096); // [512]

    const int tid = threadIdx.x;
    const int i   = tid & 255;
    const int jh  = tid >> 8;
    const int b0  = blockIdx.x * 2;

    for (int idx = tid; idx < 512 * 16; idx += 512) {
        int r = idx >> 4, cc = idx & 15;
        int ui = r & 255, uh = r >> 8;
        Wsm4[r * R5_WSTRIDE + cc] =
            *(const float4*)(Whh + (size_t)ui * 256 + uh * 128 + 64 + cc * 4);
    }
    unsigned long long wr[32];
#pragma unroll
    for (int q = 0; q < 32; q++)
        wr[q] = *(const unsigned long long*)(Whh + (size_t)i * 256 + jh * 128 + 2 * q);

    if (tid < 256) {
        ulonglong2 zz; zz.x = 0ULL; zz.y = 0ULL;
        hs2[tid] = zz;
    }
    const float a_i = (i < 86) ? 0.001f : (i < 171) ? 0.01f : 0.1f;
    float h0t = 0.0f, h1t = 0.0f;
    float z0 = 0.0f, z1 = 0.0f;
    if (tid < 256) {
        z0 = Z[(size_t)b0 * HDIM + tid];
        z1 = Z[(size_t)b0 * HDIM + 256 + tid];
    }
    __syncthreads();

    int cur = 0;
    for (int t = 0; t < TT; t++) {
        float zn0 = 0.0f, zn1 = 0.0f;
        if (tid < 256) {
            if (t + 1 < TT) {
                const float* Zn = Z + ((size_t)(t + 1) * BB + b0) * HDIM;
                zn0 = Zn[tid];
                zn1 = Zn[256 + tid];
            }
            float* Ht = Hall + ((size_t)t * BB + b0) * HDIM;
            Ht[tid] = roundtf(h0t);
            Ht[256 + tid] = roundtf(h1t);
        }

        const ulonglong2* hc = hs2 + cur * 128;
        unsigned long long A0 = 0, B0 = 0, A1 = 0, B1 = 0;

#pragma unroll
        for (int q = 0; q < 32; q += 2) {
            ulonglong2 hva = hc[jh * 64 + q];
            ulonglong2 hvb = hc[jh * 64 + q + 1];
            FMA2(A0, wr[q], hva.x);     FMA2(A1, wr[q], hva.y);
            FMA2(B0, wr[q + 1], hvb.x); FMA2(B1, wr[q + 1], hvb.y);
        }
        const ulonglong2* Wrow =
            (const ulonglong2*)(Wsm4 + (size_t)tid * R5_WSTRIDE);
#pragma unroll
        for (int cc = 0; cc < 16; cc++) {
            ulonglong2 wv  = Wrow[cc];
            ulonglong2 hva = hc[jh * 64 + 32 + 2 * cc];
            ulonglong2 hvb = hc[jh * 64 + 33 + 2 * cc];
            FMA2(A0, wv.x, hva.x); FMA2(A1, wv.x, hva.y);
            FMA2(B0, wv.y, hvb.x); FMA2(B1, wv.y, hvb.y);
        }

        ADD2(A0, B0);
        ADD2(A1, B1);
        float p0lo, p0hi, p1lo, p1hi;
        UNPACK2(p0lo, p0hi, A0);
        UNPACK2(p1lo, p1hi, A1);
        red[tid] = make_float2(p0lo + p0hi, p1lo + p1hi);
        __syncthreads();

        if (tid < 256) {
            float2 ra = red[tid], rb = red[256 + tid];
            float hr0 = tanhf(ra.x + rb.x + z0);
            float hr1 = tanhf(ra.y + rb.y + z1);
            h0t = fmaf(a_i, hr0 - h0t, h0t);
            h1t = fmaf(a_i, hr1 - h1t, h1t);
            float* hw = (float*)(hs2 + (cur ^ 1) * 128);
            hw[(tid >> 1) * 4 + (tid & 1)]     = h0t;
            hw[(tid >> 1) * 4 + (tid & 1) + 2] = h1t;
        }
        __syncthreads();
        cur ^= 1;
        z0 = zn0; z1 = zn1;
    }
}

// ---------------------------------------------------------------------------
// Launch. Input order: x,Wx0,bx0,Wx1,bx1,Wih,Whh,bih,bhh,Wh0,bh0,Wh1,bh1,Wg,bg
// ---------------------------------------------------------------------------
extern "C" void kernel_launch(void* const* d_in, const int* in_sizes, int n_in,
                              void* d_out, int out_size)
{
    const float* x   = (const float*)d_in[0];
    const float* Wx0 = (const float*)d_in[1];
    const float* bx0 = (const float*)d_in[2];
    const float* Wx1 = (const float*)d_in[3];
    const float* bx1 = (const float*)d_in[4];
    const float* Wih = (const float*)d_in[5];
    const float* Whh = (const float*)d_in[6];
    const float* bih = (const float*)d_in[7];
    const float* bhh = (const float*)d_in[8];
    const float* Wh0 = (const float*)d_in[9];
    const float* bh0 = (const float*)d_in[10];
    const float* Wh1 = (const float*)d_in[11];
    const float* bh1 = (const float*)d_in[12];
    const float* Wg  = (const float*)d_in[13];
    const float* bg  = (const float*)d_in[14];
    float* y = (float*)d_out;

    float *bufA, *bufB, *wr;
    cudaGetSymbolAddress((void**)&bufA, g_bufA);
    cudaGetSymbolAddress((void**)&bufB, g_bufB);
    cudaGetSymbolAddress((void**)&wr,  g_wr);

    auto F1 = fused3_kernel<64, 256>;    // x -> feat1 -> feat2 -> Z
    auto F2 = fused3_kernel<256, 64>;    // Hall -> d1 -> d2 -> y
    cudaFuncSetAttribute(F1, cudaFuncAttributeMaxDynamicSharedMemorySize, FUSED_SMEM);
    cudaFuncSetAttribute(F2, cudaFuncAttributeMaxDynamicSharedMemorySize, FUSED_SMEM);
    cudaFuncSetAttribute(recurrence5_kernel,
                         cudaFuncAttributeMaxDynamicSharedMemorySize, R5_SMEM_BYTES);

    // --- pre-round inputs to tf32 ---
    round_tf32_kernel<<<(MM * XDIM) / 4 / 256, 256>>>(x, bufB, MM * XDIM);
    round_tf32_kernel<<<16, 256>>>(Wx0, wr + WR_WX0, FDIM * XDIM);
    round_tf32_kernel<<<64, 256>>>(Wx1, wr + WR_WX1, FDIM * FDIM);
    round_tf32_kernel<<<64, 256>>>(Wih, wr + WR_WIH, HDIM * FDIM);
    round_tf32_kernel<<<64, 256>>>(Wh0, wr + WR_WH0, FDIM * HDIM);
    round_tf32_kernel<<<64, 256>>>(Wh1, wr + WR_WH1, FDIM * FDIM);
    round_tf32_kernel<<<16, 256>>>(Wg,  wr + WR_WG,  XDIM * FDIM);

    // Z = tanh-MLP(x) @ Wih^T + bih + bhh      (x_r in bufB -> Z in bufA)
    F1<<<MM / 128, 512, FUSED_SMEM>>>(bufB, wr + WR_WX0, bx0,
                                      wr + WR_WX1, bx1,
                                      wr + WR_WIH, bih, bhh, bufA);
    // scan: Hall[t] = round(h_t); h update     (Z in bufA -> Hall in bufB)
    recurrence5_kernel<<<BB / 2, 512, R5_SMEM_BYTES>>>(bufA, Whh, bufB);
    // y = tanh-MLP(Hall) @ Wg^T + bg           (Hall in bufB -> y)
    F2<<<MM / 128, 512, FUSED_SMEM>>>(bufB, wr + WR_WH0, bh0,
                                      wr + WR_WH1, bh1,
                                      wr + WR_WG, bg, nullptr, y);
}

// round 12
// speedup vs baseline: 1.4850x; 1.4850x over previous
#include <cuda_runtime.h>
#include <math.h>
#include <stddef.h>
#include <stdint.h>

// Problem dims
#define TT 1024
#define BB 256
#define XDIM 64
#define HDIM 256
#define FDIM 256
#define MM (TT*BB)          // 262144 rows for all big GEMMs

// ---------------------------------------------------------------------------
// Scratch (no cudaMalloc allowed)
// ---------------------------------------------------------------------------
__device__ float g_bufA[(size_t)MM * FDIM];   // 256 MB
__device__ float g_bufB[(size_t)MM * FDIM];   // 256 MB
__device__ float g_wr[294912];                // rounded weights, 1.2 MB

#define WR_WX0 0
#define WR_WX1 16384
#define WR_WIH 81920
#define WR_WH0 147456
#define WR_WH1 212992
#define WR_WG  278528

// ---------------------------------------------------------------------------
// helpers
// ---------------------------------------------------------------------------
__device__ __forceinline__ uint32_t f2tf32(float x) {
    uint32_t u;
    asm("cvt.rna.tf32.f32 %0, %1;" : "=r"(u) : "f"(x));
    return u;
}
__device__ __forceinline__ float roundtf(float x) {
    return __uint_as_float(f2tf32(x));
}

#define MMA_TF32(c, a0, a1, a2, a3, b0, b1)                                 \
    asm volatile("mma.sync.aligned.m16n8k8.row.col.f32.tf32.tf32.f32 "      \
                 "{%0,%1,%2,%3}, {%4,%5,%6,%7}, {%8,%9}, {%0,%1,%2,%3};"    \
                 : "+f"(c[0]), "+f"(c[1]), "+f"(c[2]), "+f"(c[3])           \
                 : "r"(a0), "r"(a1), "r"(a2), "r"(a3), "r"(b0), "r"(b1))

#define FMA2(d, a, b)                                                       \
    asm("fma.rn.f32x2 %0, %1, %2, %0;" : "+l"(d) : "l"(a), "l"(b))
#define ADD2(d, a)                                                          \
    asm("add.rn.f32x2 %0, %0, %1;" : "+l"(d) : "l"(a))
#define UNPACK2(lo, hi, d)                                                  \
    asm("mov.b64 {%0, %1}, %2;" : "=f"(lo), "=f"(hi) : "l"(d))

__device__ __forceinline__ void cp16(uint32_t dst, const void* src) {
    asm volatile("cp.async.ca.shared.global [%0], [%1], 16;\n"
                 :: "r"(dst), "l"(src));
}
__device__ __forceinline__ void cp_commit() {
    asm volatile("cp.async.commit_group;\n" ::);
}
template<int N>
__device__ __forceinline__ void cp_wait() {
    asm volatile("cp.async.wait_group %0;\n" :: "n"(N));
}

// ---------------------------------------------------------------------------
// Pre-round inputs to tf32 (idempotent; GEMMs then feed raw bits to mma)
// ---------------------------------------------------------------------------
__global__ void round_tf32_kernel(const float* __restrict__ src,
                                  float* __restrict__ dst, int n)
{
    int idx = (blockIdx.x * blockDim.x + threadIdx.x) * 4;
    if (idx < n) {
        float4 v = *(const float4*)(src + idx);
        v.x = roundtf(v.x); v.y = roundtf(v.y);
        v.z = roundtf(v.z); v.w = roundtf(v.w);
        *(float4*)(dst + idx) = v;
    }
}

// ---------------------------------------------------------------------------
// k-tile compute: BOTH operands from swizzled smem tiles ([rows][32], chunk c
// of row r at c^(r&7)). B rows satisfy nb&7==g so A-style indexing applies.
// ---------------------------------------------------------------------------
template<int WM_AT, int WN_AT>
__device__ __forceinline__ void comp_ss(
    const float* Asl, const float* Wsl,
    int wm, int wn, int g, int tig, float (*c)[4])
{
#pragma unroll
    for (int s = 0; s < 4; s++) {
        const int x0 = ((2 * s) ^ g) * 4 + tig;       // k = s*8+tig
        const int x1 = ((2 * s + 1) ^ g) * 4 + tig;   // k = s*8+tig+4
        uint32_t af[WM_AT][4];
#pragma unroll
        for (int mi = 0; mi < WM_AT; mi++) {
            int rb = (wm * WM_AT + mi) * 16 + g;
            af[mi][0] = __float_as_uint(Asl[rb * 32 + x0]);
            af[mi][1] = __float_as_uint(Asl[(rb + 8) * 32 + x0]);
            af[mi][2] = __float_as_uint(Asl[rb * 32 + x1]);
            af[mi][3] = __float_as_uint(Asl[(rb + 8) * 32 + x1]);
        }
        uint32_t bf[WN_AT][2];
#pragma unroll
        for (int ni = 0; ni < WN_AT; ni++) {
            int nb = (wn * WN_AT + ni) * 8 + g;
            bf[ni][0] = __float_as_uint(Wsl[nb * 32 + x0]);
            bf[ni][1] = __float_as_uint(Wsl[nb * 32 + x1]);
        }
#pragma unroll
        for (int mi = 0; mi < WM_AT; mi++)
#pragma unroll
            for (int ni = 0; ni < WN_AT; ni++)
                MMA_TF32(c[mi * WN_AT + ni], af[mi][0], af[mi][1],
                         af[mi][2], af[mi][3], bf[ni][0], bf[ni][1]);
    }
}

// Store accums (WM_AT=2, WN_AT=8 mapping) as tanh+tf32-round into the
// swizzled smem buffer S (8 k-tiles x [128][32]).
__device__ __forceinline__ void store_S_tanh(
    float* S, const float* __restrict__ bias,
    int wm, int wn, int g, int tig, float (*c)[4])
{
#pragma unroll
    for (int mi = 0; mi < 2; mi++) {
        int r0 = (wm * 2 + mi) * 16 + g;
#pragma unroll
        for (int ni = 0; ni < 8; ni++) {
            int cc = (wn * 8 + ni) * 8 + 2 * tig;
            float b0 = bias[cc], b1 = bias[cc + 1];
            float* p = c[mi * 8 + ni];
            float v0 = roundtf(tanhf(p[0] + b0));
            float v1 = roundtf(tanhf(p[1] + b1));
            float v2 = roundtf(tanhf(p[2] + b0));
            float v3 = roundtf(tanhf(p[3] + b1));
            int tilebase = (cc >> 5) * 4096;
            int swz = ((((cc >> 2) & 7)) ^ (r0 & 7)) << 2;   // r0&7 == g
            int elem = cc & 3;
            *(float2*)(S + tilebase + r0 * 32 + swz + elem) = make_float2(v0, v1);
            *(float2*)(S + tilebase + (r0 + 8) * 32 + swz + elem) = make_float2(v2, v3);
        }
    }
}

// ---------------------------------------------------------------------------
// Fused 3-layer MLP over a 128-row tile; ALL operands staged through smem:
//   S = tanh(Ain@W1^T + b1)   (K=K1, N=256)
//   S = tanh(S@W2^T + b2)     (K=256, N=256)
//   C = S@W3^T + b3 (+b3b)    (K=256, N=N3)
// 512 threads. S lives in 128KB smem; W tiles double-buffered via cp.async
// (32KB/stage); A tiles (phase A only) double-buffered (16KB/stage).
// smem total = 229376 B. Inputs must be pre-rounded to tf32 bit patterns.
// ---------------------------------------------------------------------------
#define FUSED_SMEM ((32768 + 2 * 8192 + 2 * 4096) * 4)   // 229376 B

template<int K1, int N3>
__global__ __launch_bounds__(512) void fused3_kernel(
    const float* __restrict__ Ain,
    const float* __restrict__ W1, const float* __restrict__ b1,
    const float* __restrict__ W2, const float* __restrict__ b2,
    const float* __restrict__ W3, const float* __restrict__ b3,
    const float* __restrict__ b3b,
    float* __restrict__ Cout)
{
    extern __shared__ float smf[];
    float* S    = smf;                    // 32768 floats
    float* Wbuf = smf + 32768;            // 2 stages x 8192 floats
    float* Abuf = smf + 32768 + 16384;    // 2 stages x 4096 floats

    const int tid  = threadIdx.x;
    const int warp = tid >> 5;
    const int lane = tid & 31;
    const int wm   = warp >> 2;    // 4x4 warp grid for N=256 phases
    const int wn   = warp & 3;
    const int g    = lane >> 2;
    const int tig  = lane & 3;
    const int m0   = blockIdx.x * 128;

    float c[16][4];

    auto issueA = [&](int st, int kt) {
#pragma unroll
        for (int it = 0; it < 2; it++) {
            int ch = tid + it * 512;
            int row = ch >> 3, cc = ch & 7;
            const float* src = Ain + (size_t)(m0 + row) * K1 + kt * 32 + cc * 4;
            uint32_t dst = (uint32_t)__cvta_generic_to_shared(
                Abuf + st * 4096 + row * 32 + ((cc ^ (row & 7)) << 2));
            cp16(dst, src);
        }
    };
    auto issueW = [&](const float* Wsrc, int K, int Nrows, int st, int kt) {
        for (int ch = tid; ch < Nrows * 8; ch += 512) {
            int row = ch >> 3, cc = ch & 7;
            const float* src = Wsrc + (size_t)row * K + kt * 32 + cc * 4;
            uint32_t dst = (uint32_t)__cvta_generic_to_shared(
                Wbuf + st * 8192 + row * 32 + ((cc ^ (row & 7)) << 2));
            cp16(dst, src);
        }
    };

    // ---------------- Phase A: S = tanh(Ain@W1^T + b1) ----------------
#pragma unroll
    for (int i = 0; i < 16; i++)
#pragma unroll
        for (int e = 0; e < 4; e++) c[i][e] = 0.0f;

    constexpr int KT1 = K1 / 32;           // 2 or 8
    issueA(0, 0); issueW(W1, K1, 256, 0, 0); cp_commit();
    issueA(1, 1); issueW(W1, K1, 256, 1, 1); cp_commit();
    for (int kt = 0; kt < KT1; kt++) {
        cp_wait<1>();
        __syncthreads();
        comp_ss<2, 8>(Abuf + (kt & 1) * 4096, Wbuf + (kt & 1) * 8192,
                      wm, wn, g, tig, c);
        __syncthreads();
        if (kt + 2 < KT1) { issueA(kt & 1, kt + 2); issueW(W1, K1, 256, kt & 1, kt + 2); }
        cp_commit();
    }
    cp_wait<0>();
    // prologue for phase B hidden under tanh/store
    issueW(W2, 256, 256, 0, 0); cp_commit();
    issueW(W2, 256, 256, 1, 1); cp_commit();
    store_S_tanh(S, b1, wm, wn, g, tig, c);
    __syncthreads();

    // ---------------- Phase B: S = tanh(S@W2^T + b2) ----------------
#pragma unroll
    for (int i = 0; i < 16; i++)
#pragma unroll
        for (int e = 0; e < 4; e++) c[i][e] = 0.0f;
    for (int kt = 0; kt < 8; kt++) {
        cp_wait<1>();
        __syncthreads();
        comp_ss<2, 8>(S + kt * 4096, Wbuf + (kt & 1) * 8192,
                      wm, wn, g, tig, c);
        __syncthreads();
        if (kt + 2 < 8) issueW(W2, 256, 256, kt & 1, kt + 2);
        cp_commit();
    }
    cp_wait<0>();
    // prologue for phase C hidden under tanh/store
    issueW(W3, 256, N3, 0, 0); cp_commit();
    issueW(W3, 256, N3, 1, 1); cp_commit();
    store_S_tanh(S, b2, wm, wn, g, tig, c);
    __syncthreads();

    // ---------------- Phase C: Cout = S@W3^T + b3 (+b3b) ----------------
#pragma unroll
    for (int i = 0; i < 16; i++)
#pragma unroll
        for (int e = 0; e < 4; e++) c[i][e] = 0.0f;

    if constexpr (N3 == 256) {
        for (int kt = 0; kt < 8; kt++) {
            cp_wait<1>();
            __syncthreads();
            comp_ss<2, 8>(S + kt * 4096, Wbuf + (kt & 1) * 8192,
                          wm, wn, g, tig, c);
            __syncthreads();
            if (kt + 2 < 8) issueW(W3, 256, 256, kt & 1, kt + 2);
            cp_commit();
        }
        cp_wait<0>();
#pragma unroll
        for (int mi = 0; mi < 2; mi++) {
            int r0 = m0 + (wm * 2 + mi) * 16 + g;
#pragma unroll
            for (int ni = 0; ni < 8; ni++) {
                int cc = (wn * 8 + ni) * 8 + 2 * tig;
                float b0v = b3[cc], b1v = b3[cc + 1];
                if (b3b) { b0v += b3b[cc]; b1v += b3b[cc + 1]; }
                float* p = c[mi * 8 + ni];
                *(float2*)(Cout + (size_t)r0 * 256 + cc) =
                    make_float2(p[0] + b0v, p[1] + b1v);
                *(float2*)(Cout + (size_t)(r0 + 8) * 256 + cc) =
                    make_float2(p[2] + b0v, p[3] + b1v);
            }
        }
    } else {
        // N3 = 64: 8x2 warp grid, WM_AT=1, WN_AT=4
        const int wm3 = warp >> 1;
        const int wn3 = warp & 1;
        for (int kt = 0; kt < 8; kt++) {
            cp_wait<1>();
            __syncthreads();
            comp_ss<1, 4>(S + kt * 4096, Wbuf + (kt & 1) * 8192,
                          wm3, wn3, g, tig, c);
            __syncthreads();
            if (kt + 2 < 8) issueW(W3, 256, N3, kt & 1, kt + 2);
            cp_commit();
        }
        cp_wait<0>();
        int r0 = m0 + wm3 * 16 + g;
#pragma unroll
        for (int ni = 0; ni < 4; ni++) {
            int cc = (wn3 * 4 + ni) * 8 + 2 * tig;
            float b0v = b3[cc], b1v = b3[cc + 1];
            float* p = c[ni];
            *(float2*)(Cout + (size_t)r0 * 64 + cc) =
                make_float2(p[0] + b0v, p[1] + b1v);
            *(float2*)(Cout + (size_t)(r0 + 8) * 64 + cc) =
                make_float2(p[2] + b0v, p[3] + b1v);
        }
    }
}

// ---------------------------------------------------------------------------
// Recurrence v5 (unchanged from R8). 128 blocks x 512 threads, 2 batch rows.
// ---------------------------------------------------------------------------
#define R5_WSTRIDE 17
#define R5_SMEM_BYTES (512*R5_WSTRIDE*16 + 2*128*16 + 512*8)  // 147456 B

__global__ __launch_bounds__(512, 1) void recurrence5_kernel(
    const float* __restrict__ Z, const float* __restrict__ Whh,
    float* __restrict__ Hall)
{
    extern __shared__ unsigned char rsm[];
    float4*     Wsm4 = (float4*)rsm;                               // [512][17]
    ulonglong2* hs2  = (ulonglong2*)(rsm + 512 * R5_WSTRIDE * 16); // [2][128]
    float2*     red  = (float2*)(rsm + 512 * R5_WSTRIDE * 16 + 4096); // [512]

    const int tid = threadIdx.x;
    const int i   = tid & 255;
    const int jh  = tid >> 8;
    const int b0  = blockIdx.x * 2;

    for (int idx = tid; idx < 512 * 16; idx += 512) {
        int r = idx >> 4, cc = idx & 15;
        int ui = r & 255, uh = r >> 8;
        Wsm4[r * R5_WSTRIDE + cc] =
            *(const float4*)(Whh + (size_t)ui * 256 + uh * 128 + 64 + cc * 4);
    }
    unsigned long long wr[32];
#pragma unroll
    for (int q = 0; q < 32; q++)
        wr[q] = *(const unsigned long long*)(Whh + (size_t)i * 256 + jh * 128 + 2 * q);

    if (tid < 256) {
        ulonglong2 zz; zz.x = 0ULL; zz.y = 0ULL;
        hs2[tid] = zz;
    }
    const float a_i = (i < 86) ? 0.001f : (i < 171) ? 0.01f : 0.1f;
    float h0t = 0.0f, h1t = 0.0f;
    float z0 = 0.0f, z1 = 0.0f;
    if (tid < 256) {
        z0 = Z[(size_t)b0 * HDIM + tid];
        z1 = Z[(size_t)b0 * HDIM + 256 + tid];
    }
    __syncthreads();

    int cur = 0;
    for (int t = 0; t < TT; t++) {
        float zn0 = 0.0f, zn1 = 0.0f;
        if (tid < 256) {
            if (t + 1 < TT) {
                const float* Zn = Z + ((size_t)(t + 1) * BB + b0) * HDIM;
                zn0 = Zn[tid];
                zn1 = Zn[256 + tid];
            }
            float* Ht = Hall + ((size_t)t * BB + b0) * HDIM;
            Ht[tid] = roundtf(h0t);
            Ht[256 + tid] = roundtf(h1t);
        }

        const ulonglong2* hc = hs2 + cur * 128;
        unsigned long long A0 = 0, B0 = 0, A1 = 0, B1 = 0;

#pragma unroll
        for (int q = 0; q < 32; q += 2) {
            ulonglong2 hva = hc[jh * 64 + q];
            ulonglong2 hvb = hc[jh * 64 + q + 1];
            FMA2(A0, wr[q], hva.x);     FMA2(A1, wr[q], hva.y);
            FMA2(B0, wr[q + 1], hvb.x); FMA2(B1, wr[q + 1], hvb.y);
        }
        const ulonglong2* Wrow =
            (const ulonglong2*)(Wsm4 + (size_t)tid * R5_WSTRIDE);
#pragma unroll
        for (int cc = 0; cc < 16; cc++) {
            ulonglong2 wv  = Wrow[cc];
            ulonglong2 hva = hc[jh * 64 + 32 + 2 * cc];
            ulonglong2 hvb = hc[jh * 64 + 33 + 2 * cc];
            FMA2(A0, wv.x, hva.x); FMA2(A1, wv.x, hva.y);
            FMA2(B0, wv.y, hvb.x); FMA2(B1, wv.y, hvb.y);
        }

        ADD2(A0, B0);
        ADD2(A1, B1);
        float p0lo, p0hi, p1lo, p1hi;
        UNPACK2(p0lo, p0hi, A0);
        UNPACK2(p1lo, p1hi, A1);
        red[tid] = make_float2(p0lo + p0hi, p1lo + p1hi);
        __syncthreads();

        if (tid < 256) {
            float2 ra = red[tid], rb = red[256 + tid];
            float hr0 = tanhf(ra.x + rb.x + z0);
            float hr1 = tanhf(ra.y + rb.y + z1);
            h0t = fmaf(a_i, hr0 - h0t, h0t);
            h1t = fmaf(a_i, hr1 - h1t, h1t);
            float* hw = (float*)(hs2 + (cur ^ 1) * 128);
            hw[(tid >> 1) * 4 + (tid & 1)]     = h0t;
            hw[(tid >> 1) * 4 + (tid & 1) + 2] = h1t;
        }
        __syncthreads();
        cur ^= 1;
        z0 = zn0; z1 = zn1;
    }
}

// ---------------------------------------------------------------------------
// Launch. Input order: x,Wx0,bx0,Wx1,bx1,Wih,Whh,bih,bhh,Wh0,bh0,Wh1,bh1,Wg,bg
// ---------------------------------------------------------------------------
extern "C" void kernel_launch(void* const* d_in, const int* in_sizes, int n_in,
                              void* d_out, int out_size)
{
    const float* x   = (const float*)d_in[0];
    const float* Wx0 = (const float*)d_in[1];
    const float* bx0 = (const float*)d_in[2];
    const float* Wx1 = (const float*)d_in[3];
    const float* bx1 = (const float*)d_in[4];
    const float* Wih = (const float*)d_in[5];
    const float* Whh = (const float*)d_in[6];
    const float* bih = (const float*)d_in[7];
    const float* bhh = (const float*)d_in[8];
    const float* Wh0 = (const float*)d_in[9];
    const float* bh0 = (const float*)d_in[10];
    const float* Wh1 = (const float*)d_in[11];
    const float* bh1 = (const float*)d_in[12];
    const float* Wg  = (const float*)d_in[13];
    const float* bg  = (const float*)d_in[14];
    float* y = (float*)d_out;

    float *bufA, *bufB, *wr;
    cudaGetSymbolAddress((void**)&bufA, g_bufA);
    cudaGetSymbolAddress((void**)&bufB, g_bufB);
    cudaGetSymbolAddress((void**)&wr,  g_wr);

    auto F1 = fused3_kernel<64, 256>;    // x -> feat1 -> feat2 -> Z
    auto F2 = fused3_kernel<256, 64>;    // Hall -> d1 -> d2 -> y
    cudaFuncSetAttribute(F1, cudaFuncAttributeMaxDynamicSharedMemorySize, FUSED_SMEM);
    cudaFuncSetAttribute(F2, cudaFuncAttributeMaxDynamicSharedMemorySize, FUSED_SMEM);
    cudaFuncSetAttribute(recurrence5_kernel,
                         cudaFuncAttributeMaxDynamicSharedMemorySize, R5_SMEM_BYTES);

    // --- pre-round inputs to tf32 ---
    round_tf32_kernel<<<(MM * XDIM) / 4 / 256, 256>>>(x, bufB, MM * XDIM);
    round_tf32_kernel<<<16, 256>>>(Wx0, wr + WR_WX0, FDIM * XDIM);
    round_tf32_kernel<<<64, 256>>>(Wx1, wr + WR_WX1, FDIM * FDIM);
    round_tf32_kernel<<<64, 256>>>(Wih, wr + WR_WIH, HDIM * FDIM);
    round_tf32_kernel<<<64, 256>>>(Wh0, wr + WR_WH0, FDIM * HDIM);
    round_tf32_kernel<<<64, 256>>>(Wh1, wr + WR_WH1, FDIM * FDIM);
    round_tf32_kernel<<<16, 256>>>(Wg,  wr + WR_WG,  XDIM * FDIM);

    // Z = tanh-MLP(x) @ Wih^T + bih + bhh      (x_r in bufB -> Z in bufA)
    F1<<<MM / 128, 512, FUSED_SMEM>>>(bufB, wr + WR_WX0, bx0,
                                      wr + WR_WX1, bx1,
                                      wr + WR_WIH, bih, bhh, bufA);
    // scan: Hall[t] = round(h_t); h update     (Z in bufA -> Hall in bufB)
    recurrence5_kernel<<<BB / 2, 512, R5_SMEM_BYTES>>>(bufA, Whh, bufB);
    // y = tanh-MLP(Hall) @ Wg^T + bg           (Hall in bufB -> y)
    F2<<<MM / 128, 512, FUSED_SMEM>>>(bufB, wr + WR_WH0, bh0,
                                      wr + WR_WH1, bh1,
                                      wr + WR_WG, bg, nullptr, y);
}

// round 17
// speedup vs baseline: 1.5391x; 1.0364x over previous
#include <cuda_runtime.h>
#include <math.h>
#include <stddef.h>
#include <stdint.h>

// Problem dims
#define TT 1024
#define BB 256
#define XDIM 64
#define HDIM 256
#define FDIM 256
#define MM (TT*BB)          // 262144 rows for all big GEMMs

// ---------------------------------------------------------------------------
// Scratch (no cudaMalloc allowed)
// ---------------------------------------------------------------------------
__device__ float g_bufA[(size_t)MM * FDIM];   // 256 MB
__device__ float g_bufB[(size_t)MM * FDIM];   // 256 MB
__device__ float g_wr[294912];                // rounded weights, 1.2 MB

#define WR_WX0 0
#define WR_WX1 16384
#define WR_WIH 81920
#define WR_WH0 147456
#define WR_WH1 212992
#define WR_WG  278528

// ---------------------------------------------------------------------------
// helpers
// ---------------------------------------------------------------------------
__device__ __forceinline__ uint32_t f2tf32(float x) {
    uint32_t u;
    asm("cvt.rna.tf32.f32 %0, %1;" : "=r"(u) : "f"(x));
    return u;
}
__device__ __forceinline__ float roundtf(float x) {
    return __uint_as_float(f2tf32(x));
}

#define MMA_TF32(c, a0, a1, a2, a3, b0, b1)                                 \
    asm volatile("mma.sync.aligned.m16n8k8.row.col.f32.tf32.tf32.f32 "      \
                 "{%0,%1,%2,%3}, {%4,%5,%6,%7}, {%8,%9}, {%0,%1,%2,%3};"    \
                 : "+f"(c[0]), "+f"(c[1]), "+f"(c[2]), "+f"(c[3])           \
                 : "r"(a0), "r"(a1), "r"(a2), "r"(a3), "r"(b0), "r"(b1))

#define FMA2(d, a, b)                                                       \
    asm("fma.rn.f32x2 %0, %1, %2, %0;" : "+l"(d) : "l"(a), "l"(b))
#define ADD2(d, a)                                                          \
    asm("add.rn.f32x2 %0, %0, %1;" : "+l"(d) : "l"(a))
#define UNPACK2(lo, hi, d)                                                  \
    asm("mov.b64 {%0, %1}, %2;" : "=f"(lo), "=f"(hi) : "l"(d))

__device__ __forceinline__ void cp16(uint32_t dst, const void* src) {
    asm volatile("cp.async.ca.shared.global [%0], [%1], 16;\n"
                 :: "r"(dst), "l"(src));
}
__device__ __forceinline__ void cp_commit() {
    asm volatile("cp.async.commit_group;\n" ::);
}
template<int N>
__device__ __forceinline__ void cp_wait() {
    asm volatile("cp.async.wait_group %0;\n" :: "n"(N));
}

// ---------------------------------------------------------------------------
// Rounding prepass: 2 launches total (x big pass, all weights in one pass)
// ---------------------------------------------------------------------------
__global__ void round_x_kernel(const float* __restrict__ src,
                               float* __restrict__ dst, int n)
{
    int idx = (blockIdx.x * blockDim.x + threadIdx.x) * 4;
    if (idx < n) {
        float4 v = *(const float4*)(src + idx);
        v.x = roundtf(v.x); v.y = roundtf(v.y);
        v.z = roundtf(v.z); v.w = roundtf(v.w);
        *(float4*)(dst + idx) = v;
    }
}

__global__ void round_weights_kernel(
    const float* __restrict__ w0, const float* __restrict__ w1,
    const float* __restrict__ w2, const float* __restrict__ w3,
    const float* __restrict__ w4, const float* __restrict__ w5,
    float* __restrict__ dst)
{
    // region sizes in float4: 4096,16384,16384,16384,16384,4096 (sum 73728)
    int idx = blockIdx.x * blockDim.x + threadIdx.x;   // 0..73727 (f4 units)
    if (idx >= 73728) return;
    const float* src;
    int off;
    if      (idx < 4096)  { src = w0; off = idx; }
    else if (idx < 20480) { src = w1; off = idx - 4096; }
    else if (idx < 36864) { src = w2; off = idx - 20480; }
    else if (idx < 53248) { src = w3; off = idx - 36864; }
    else if (idx < 69632) { src = w4; off = idx - 53248; }
    else                  { src = w5; off = idx - 69632; }
    float4 v = *(const float4*)(src + off * 4);
    v.x = roundtf(v.x); v.y = roundtf(v.y);
    v.z = roundtf(v.z); v.w = roundtf(v.w);
    *(float4*)(dst + idx * 4) = v;
}

// ---------------------------------------------------------------------------
// k-tile compute: BOTH operands from swizzled smem tiles ([rows][32], chunk c
// of row r at c^(r&7)). B rows satisfy nb&7==g so A-style indexing applies.
// ---------------------------------------------------------------------------
template<int WM_AT, int WN_AT>
__device__ __forceinline__ void comp_ss(
    const float* Asl, const float* Wsl,
    int wm, int wn, int g, int tig, float (*c)[4])
{
#pragma unroll
    for (int s = 0; s < 4; s++) {
        const int x0 = ((2 * s) ^ g) * 4 + tig;
        const int x1 = ((2 * s + 1) ^ g) * 4 + tig;
        uint32_t af[WM_AT][4];
#pragma unroll
        for (int mi = 0; mi < WM_AT; mi++) {
            int rb = (wm * WM_AT + mi) * 16 + g;
            af[mi][0] = __float_as_uint(Asl[rb * 32 + x0]);
            af[mi][1] = __float_as_uint(Asl[(rb + 8) * 32 + x0]);
            af[mi][2] = __float_as_uint(Asl[rb * 32 + x1]);
            af[mi][3] = __float_as_uint(Asl[(rb + 8) * 32 + x1]);
        }
        uint32_t bf[WN_AT][2];
#pragma unroll
        for (int ni = 0; ni < WN_AT; ni++) {
            int nb = (wn * WN_AT + ni) * 8 + g;
            bf[ni][0] = __float_as_uint(Wsl[nb * 32 + x0]);
            bf[ni][1] = __float_as_uint(Wsl[nb * 32 + x1]);
        }
#pragma unroll
        for (int mi = 0; mi < WM_AT; mi++)
#pragma unroll
            for (int ni = 0; ni < WN_AT; ni++)
                MMA_TF32(c[mi * WN_AT + ni], af[mi][0], af[mi][1],
                         af[mi][2], af[mi][3], bf[ni][0], bf[ni][1]);
    }
}

// Store accums (WM_AT=2, WN_AT=8 mapping) as tanh+tf32-round into S.
__device__ __forceinline__ void store_S_tanh(
    float* S, const float* __restrict__ bias,
    int wm, int wn, int g, int tig, float (*c)[4])
{
#pragma unroll
    for (int mi = 0; mi < 2; mi++) {
        int r0 = (wm * 2 + mi) * 16 + g;
#pragma unroll
        for (int ni = 0; ni < 8; ni++) {
            int cc = (wn * 8 + ni) * 8 + 2 * tig;
            float b0 = bias[cc], b1 = bias[cc + 1];
            float* p = c[mi * 8 + ni];
            float v0 = roundtf(tanhf(p[0] + b0));
            float v1 = roundtf(tanhf(p[1] + b1));
            float v2 = roundtf(tanhf(p[2] + b0));
            float v3 = roundtf(tanhf(p[3] + b1));
            int tilebase = (cc >> 5) * 4096;
            int swz = ((((cc >> 2) & 7)) ^ (r0 & 7)) << 2;
            int elem = cc & 3;
            *(float2*)(S + tilebase + r0 * 32 + swz + elem) = make_float2(v0, v1);
            *(float2*)(S + tilebase + (r0 + 8) * 32 + swz + elem) = make_float2(v2, v3);
        }
    }
}

// ---------------------------------------------------------------------------
// Fused 3-layer MLP over a 128-row tile.
//   S = tanh(Ain@W1^T + b1)   (K=K1, N=256)
//   S = tanh(S@W2^T + b2)     (K=256, N=256)
//   C = S@W3^T + b3 (+b3b)    (K=256, N=N3)
// smem: S 128KB @0; ring region R 96KB @32768 floats.
//  - F1 (K1=64): phase A fully resident in R (A 32KB + W1 64KB), 0 inner syncs
//  - F2 (K1=256): phase A streams A (2x16KB) + W (2x32KB), 2 syncs/k-tile
//  - phases B/C: W 3-stage ring (3x32KB) -> ONE sync per k-tile
// ---------------------------------------------------------------------------
#define FUSED_SMEM ((32768 + 24576) * 4)   // 229376 B

template<int K1, int N3>
__global__ __launch_bounds__(512) void fused3_kernel(
    const float* __restrict__ Ain,
    const float* __restrict__ W1, const float* __restrict__ b1,
    const float* __restrict__ W2, const float* __restrict__ b2,
    const float* __restrict__ W3, const float* __restrict__ b3,
    const float* __restrict__ b3b,
    float* __restrict__ Cout)
{
    extern __shared__ float smf[];
    float* S = smf;              // 32768 floats
    float* R = smf + 32768;      // 24576 floats (96KB ring / resident region)

    const int tid  = threadIdx.x;
    const int warp = tid >> 5;
    const int lane = tid & 31;
    const int wm   = warp >> 2;
    const int wn   = warp & 3;
    const int g    = lane >> 2;
    const int tig  = lane & 3;
    const int m0   = blockIdx.x * 128;

    float c[16][4];

    // generic: copy a [Nrows][32] k-tile of W (row-major [Nrows][K]) into dst
    auto issueW = [&](const float* Wsrc, int K, int Nrows, float* dst, int kt) {
        for (int ch = tid; ch < Nrows * 8; ch += 512) {
            int row = ch >> 3, cc = ch & 7;
            const float* src = Wsrc + (size_t)row * K + kt * 32 + cc * 4;
            uint32_t d = (uint32_t)__cvta_generic_to_shared(
                dst + row * 32 + ((cc ^ (row & 7)) << 2));
            cp16(d, src);
        }
    };
    auto issueA = [&](float* dst, int kt) {   // [128][32] tile of Ain
#pragma unroll
        for (int it = 0; it < 2; it++) {
            int ch = tid + it * 512;
            int row = ch >> 3, cc = ch & 7;
            const float* src = Ain + (size_t)(m0 + row) * K1 + kt * 32 + cc * 4;
            uint32_t d = (uint32_t)__cvta_generic_to_shared(
                dst + row * 32 + ((cc ^ (row & 7)) << 2));
            cp16(d, src);
        }
    };

    // ---------------- Phase A: S = tanh(Ain@W1^T + b1) ----------------
#pragma unroll
    for (int i = 0; i < 16; i++)
#pragma unroll
        for (int e = 0; e < 4; e++) c[i][e] = 0.0f;

    if constexpr (K1 == 64) {
        // fully resident: A tiles @R[0,8192), W1 tiles @R[8192,24576)
        issueA(R, 0);
        issueA(R + 4096, 1);
        issueW(W1, 64, 256, R + 8192, 0);
        issueW(W1, 64, 256, R + 16384, 1);
        cp_commit();
        cp_wait<0>();
        __syncthreads();
        comp_ss<2, 8>(R, R + 8192, wm, wn, g, tig, c);
        comp_ss<2, 8>(R + 4096, R + 16384, wm, wn, g, tig, c);
        __syncthreads();            // done reading R before W2 prologue
    } else {
        // streaming: A 2-stage @R[0,8192), W 2-stage @R[8192,24576)
        issueA(R, 0);             issueW(W1, K1, 256, R + 8192, 0);  cp_commit();
        issueA(R + 4096, 1);      issueW(W1, K1, 256, R + 16384, 1); cp_commit();
        constexpr int KT1 = K1 / 32;   // 8
        for (int kt = 0; kt < KT1; kt++) {
            cp_wait<1>();
            __syncthreads();
            comp_ss<2, 8>(R + (kt & 1) * 4096, R + 8192 + (kt & 1) * 8192,
                          wm, wn, g, tig, c);
            __syncthreads();
            if (kt + 2 < KT1) {
                issueA(R + (kt & 1) * 4096, kt + 2);
                issueW(W1, K1, 256, R + 8192 + (kt & 1) * 8192, kt + 2);
            }
            cp_commit();
        }
        cp_wait<0>();
        __syncthreads();            // all comp done before W2 prologue
    }

    // W2 prologue into ring stages 0,1 (latency hidden under tanh/store)
    issueW(W2, 256, 256, R, 0);        cp_commit();
    issueW(W2, 256, 256, R + 8192, 1); cp_commit();
    store_S_tanh(S, b1, wm, wn, g, tig, c);
    __syncthreads();

    // ---------------- Phase B: S = tanh(S@W2^T + b2) — 1 sync/k-tile ----
#pragma unroll
    for (int i = 0; i < 16; i++)
#pragma unroll
        for (int e = 0; e < 4; e++) c[i][e] = 0.0f;
    for (int kt = 0; kt < 8; kt++) {
        cp_wait<1>();
        __syncthreads();       // data visible; stage (kt+2)%3 free (read @kt-1)
        if (kt + 2 < 8) issueW(W2, 256, 256, R + ((kt + 2) % 3) * 8192, kt + 2);
        cp_commit();
        comp_ss<2, 8>(S + kt * 4096, R + (kt % 3) * 8192, wm, wn, g, tig, c);
    }
    __syncthreads();            // all comp done before W3 prologue
    issueW(W3, 256, N3, R, 0);        cp_commit();
    issueW(W3, 256, N3, R + 8192, 1); cp_commit();
    store_S_tanh(S, b2, wm, wn, g, tig, c);
    __syncthreads();

    // ---------------- Phase C: Cout = S@W3^T + b3 (+b3b) — 1 sync/k-tile -
#pragma unroll
    for (int i = 0; i < 16; i++)
#pragma unroll
        for (int e = 0; e < 4; e++) c[i][e] = 0.0f;

    if constexpr (N3 == 256) {
        for (int kt = 0; kt < 8; kt++) {
            cp_wait<1>();
            __syncthreads();
            if (kt + 2 < 8) issueW(W3, 256, 256, R + ((kt + 2) % 3) * 8192, kt + 2);
            cp_commit();
            comp_ss<2, 8>(S + kt * 4096, R + (kt % 3) * 8192, wm, wn, g, tig, c);
        }
        cp_wait<0>();
#pragma unroll
        for (int mi = 0; mi < 2; mi++) {
            int r0 = m0 + (wm * 2 + mi) * 16 + g;
#pragma unroll
            for (int ni = 0; ni < 8; ni++) {
                int cc = (wn * 8 + ni) * 8 + 2 * tig;
                float b0v = b3[cc], b1v = b3[cc + 1];
                if (b3b) { b0v += b3b[cc]; b1v += b3b[cc + 1]; }
                float* p = c[mi * 8 + ni];
                *(float2*)(Cout + (size_t)r0 * 256 + cc) =
                    make_float2(p[0] + b0v, p[1] + b1v);
                *(float2*)(Cout + (size_t)(r0 + 8) * 256 + cc) =
                    make_float2(p[2] + b0v, p[3] + b1v);
            }
        }
    } else {
        const int wm3 = warp >> 1;
        const int wn3 = warp & 1;
        for (int kt = 0; kt < 8; kt++) {
            cp_wait<1>();
            __syncthreads();
            if (kt + 2 < 8) issueW(W3, 256, N3, R + ((kt + 2) % 3) * 8192, kt + 2);
            cp_commit();
            comp_ss<1, 4>(S + kt * 4096, R + (kt % 3) * 8192, wm3, wn3, g, tig, c);
        }
        cp_wait<0>();
        int r0 = m0 + wm3 * 16 + g;
#pragma unroll
        for (int ni = 0; ni < 4; ni++) {
            int cc = (wn3 * 4 + ni) * 8 + 2 * tig;
            float b0v = b3[cc], b1v = b3[cc + 1];
            float* p = c[ni];
            *(float2*)(Cout + (size_t)r0 * 64 + cc) =
                make_float2(p[0] + b0v, p[1] + b1v);
            *(float2*)(Cout + (size_t)(r0 + 8) * 64 + cc) =
                make_float2(p[2] + b0v, p[3] + b1v);
        }
    }
}

// ---------------------------------------------------------------------------
// Recurrence v6. 128 blocks x 512 threads; block owns 2 batch rows.
// Thread (i = tid&255, jh = tid>>8): unit i, j-half jh, both batches.
// W[i][jh*128 .. +80) in 40 ull REGISTERS (~113 regs total, <128 cap);
// W[i][jh*128+80 .. +128) in smem (96KB, stride-13 float4 -> conflict-free).
// h pair-interleaved; ping-pong; 2-way j reduction via smem.
// ---------------------------------------------------------------------------
#define R6_WSTRIDE 13
#define R6_SMEM_BYTES (512*R6_WSTRIDE*16 + 2*128*16 + 512*8)  // 114688 B

__global__ __launch_bounds__(512, 1) void recurrence6_kernel(
    const float* __restrict__ Z, const float* __restrict__ Whh,
    float* __restrict__ Hall)
{
    extern __shared__ unsigned char rsm[];
    float4*     Wsm4 = (float4*)rsm;                               // [512][13] (12 used)
    ulonglong2* hs2  = (ulonglong2*)(rsm + 512 * R6_WSTRIDE * 16); // [2][128]
    float2*     red  = (float2*)(rsm + 512 * R6_WSTRIDE * 16 + 4096); // [512]

    const int tid = threadIdx.x;
    const int i   = tid & 255;
    const int jh  = tid >> 8;
    const int b0  = blockIdx.x * 2;

    // W smem part: row r=(jh*256+i) holds cols [jh*128+80, jh*128+128)
    for (int idx = tid; idx < 512 * 12; idx += 512) {
        int r = idx / 12, cc = idx % 12;
        int ui = r & 255, uh = r >> 8;
        Wsm4[r * R6_WSTRIDE + cc] =
            *(const float4*)(Whh + (size_t)ui * 256 + uh * 128 + 80 + cc * 4);
    }
    // W reg part: cols [jh*128, jh*128+80) as 40 packed pairs
    unsigned long long wr[40];
#pragma unroll
    for (int q = 0; q < 40; q++)
        wr[q] = *(const unsigned long long*)(Whh + (size_t)i * 256 + jh * 128 + 2 * q);

    if (tid < 256) {
        ulonglong2 zz; zz.x = 0ULL; zz.y = 0ULL;
        hs2[tid] = zz;
    }
    const float a_i = (i < 86) ? 0.001f : (i < 171) ? 0.01f : 0.1f;
    float h0t = 0.0f, h1t = 0.0f;
    float z0 = 0.0f, z1 = 0.0f;
    if (tid < 256) {
        z0 = Z[(size_t)b0 * HDIM + tid];
        z1 = Z[(size_t)b0 * HDIM + 256 + tid];
    }
    __syncthreads();

    int cur = 0;
    for (int t = 0; t < TT; t++) {
        float zn0 = 0.0f, zn1 = 0.0f;
        if (tid < 256) {
            if (t + 1 < TT) {
                const float* Zn = Z + ((size_t)(t + 1) * BB + b0) * HDIM;
                zn0 = Zn[tid];
                zn1 = Zn[256 + tid];
            }
            float* Ht = Hall + ((size_t)t * BB + b0) * HDIM;
            Ht[tid] = roundtf(h0t);
            Ht[256 + tid] = roundtf(h1t);
        }

        const ulonglong2* hc = hs2 + cur * 128;
        unsigned long long A0 = 0, B0 = 0, A1 = 0, B1 = 0;

        // register-resident W: pairs 0..39 of this j-half
#pragma unroll
        for (int q = 0; q < 40; q += 2) {
            ulonglong2 hva = hc[jh * 64 + q];
            ulonglong2 hvb = hc[jh * 64 + q + 1];
            FMA2(A0, wr[q], hva.x);     FMA2(A1, wr[q], hva.y);
            FMA2(B0, wr[q + 1], hvb.x); FMA2(B1, wr[q + 1], hvb.y);
        }
        // smem-resident W: pairs 40..63 (12 chunks of 2 pairs)
        const ulonglong2* Wrow =
            (const ulonglong2*)(Wsm4 + (size_t)tid * R6_WSTRIDE);
#pragma unroll
        for (int cc = 0; cc < 12; cc++) {
            ulonglong2 wv  = Wrow[cc];
            ulonglong2 hva = hc[jh * 64 + 40 + 2 * cc];
            ulonglong2 hvb = hc[jh * 64 + 41 + 2 * cc];
            FMA2(A0, wv.x, hva.x); FMA2(A1, wv.x, hva.y);
            FMA2(B0, wv.y, hvb.x); FMA2(B1, wv.y, hvb.y);
        }

        ADD2(A0, B0);
        ADD2(A1, B1);
        float p0lo, p0hi, p1lo, p1hi;
        UNPACK2(p0lo, p0hi, A0);
        UNPACK2(p1lo, p1hi, A1);
        red[tid] = make_float2(p0lo + p0hi, p1lo + p1hi);
        __syncthreads();

        if (tid < 256) {
            float2 ra = red[tid], rb = red[256 + tid];
            float hr0 = tanhf(ra.x + rb.x + z0);
            float hr1 = tanhf(ra.y + rb.y + z1);
            h0t = fmaf(a_i, hr0 - h0t, h0t);
            h1t = fmaf(a_i, hr1 - h1t, h1t);
            float* hw = (float*)(hs2 + (cur ^ 1) * 128);
            hw[(tid >> 1) * 4 + (tid & 1)]     = h0t;
            hw[(tid >> 1) * 4 + (tid & 1) + 2] = h1t;
        }
        __syncthreads();
        cur ^= 1;
        z0 = zn0; z1 = zn1;
    }
}

// ---------------------------------------------------------------------------
// Launch. Input order: x,Wx0,bx0,Wx1,bx1,Wih,Whh,bih,bhh,Wh0,bh0,Wh1,bh1,Wg,bg
// ---------------------------------------------------------------------------
extern "C" void kernel_launch(void* const* d_in, const int* in_sizes, int n_in,
                              void* d_out, int out_size)
{
    const float* x   = (const float*)d_in[0];
    const float* Wx0 = (const float*)d_in[1];
    const float* bx0 = (const float*)d_in[2];
    const float* Wx1 = (const float*)d_in[3];
    const float* bx1 = (const float*)d_in[4];
    const float* Wih = (const float*)d_in[5];
    const float* Whh = (const float*)d_in[6];
    const float* bih = (const float*)d_in[7];
    const float* bhh = (const float*)d_in[8];
    const float* Wh0 = (const float*)d_in[9];
    const float* bh0 = (const float*)d_in[10];
    const float* Wh1 = (const float*)d_in[11];
    const float* bh1 = (const float*)d_in[12];
    const float* Wg  = (const float*)d_in[13];
    const float* bg  = (const float*)d_in[14];
    float* y = (float*)d_out;

    float *bufA, *bufB, *wr;
    cudaGetSymbolAddress((void**)&bufA, g_bufA);
    cudaGetSymbolAddress((void**)&bufB, g_bufB);
    cudaGetSymbolAddress((void**)&wr,  g_wr);

    auto F1 = fused3_kernel<64, 256>;    // x -> feat1 -> feat2 -> Z
    auto F2 = fused3_kernel<256, 64>;    // Hall -> d1 -> d2 -> y
    cudaFuncSetAttribute(F1, cudaFuncAttributeMaxDynamicSharedMemorySize, FUSED_SMEM);
    cudaFuncSetAttribute(F2, cudaFuncAttributeMaxDynamicSharedMemorySize, FUSED_SMEM);
    cudaFuncSetAttribute(recurrence6_kernel,
                         cudaFuncAttributeMaxDynamicSharedMemorySize, R6_SMEM_BYTES);

    // --- pre-round inputs to tf32 (2 launches) ---
    round_x_kernel<<<(MM * XDIM) / 4 / 256, 256>>>(x, bufB, MM * XDIM);
    round_weights_kernel<<<288, 256>>>(Wx0, Wx1, Wih, Wh0, Wh1, Wg, wr);

    // Z = tanh-MLP(x) @ Wih^T + bih + bhh      (x_r in bufB -> Z in bufA)
    F1<<<MM / 128, 512, FUSED_SMEM>>>(bufB, wr + WR_WX0, bx0,
                                      wr + WR_WX1, bx1,
                                      wr + WR_WIH, bih, bhh, bufA);
    // scan: Hall[t] = round(h_t); h update     (Z in bufA -> Hall in bufB)
    recurrence6_kernel<<<BB / 2, 512, R6_SMEM_BYTES>>>(bufA, Whh, bufB);
    // y = tanh-MLP(Hall) @ Wg^T + bg           (Hall in bufB -> y)
    F2<<<MM / 128, 512, FUSED_SMEM>>>(bufB, wr + WR_WH0, bh0,
                                      wr + WR_WH1, bh1,
                                      wr + WR_WG, bg, nullptr, y);
}